// round 6
// baseline (speedup 1.0000x reference)
#include <cuda_runtime.h>

#define D 128
#define NN 50000

// ---------------- device scratch (no runtime allocation allowed) -------------
__device__ float g_agg[3][(size_t)NN * D];   // per-relation scatter accumulators
__device__ int   g_cnt[3][NN];               // per-relation in-degree counts
__device__ float g_WT[5 * D * D];            // transposed / pre-scaled weights
                                             // [0]=Wl_rates^T [1]=Wr_rates^T
                                             // [2]=.5*Wl_rev^T [3]=.5*Wl_fol^T [4]=.5*(Wr_rev+Wr_fol)^T
__device__ float g_bias[2 * D];              // [0:D)=bl_rates, [D:2D)=.5*(bl_rev+bl_fol)

// ---------------- zero the accumulators (every launch; must be deterministic)
__global__ void zero_kernel() {
    size_t stride = (size_t)gridDim.x * blockDim.x;
    size_t i = (size_t)blockIdx.x * blockDim.x + threadIdx.x;
    float4* p = (float4*)g_agg;
    const size_t n4 = (size_t)3 * NN * D / 4;
    for (size_t j = i; j < n4; j += stride) p[j] = make_float4(0.f, 0.f, 0.f, 0.f);
    int4* q = (int4*)g_cnt;
    const size_t c4 = (size_t)3 * NN / 4;   // 150000/4, exact
    for (size_t j = i; j < c4; j += stride) q[j] = make_int4(0, 0, 0, 0);
}

// ---------------- build transposed & pre-scaled weights + fused biases -------
__global__ void prep_kernel(const float* __restrict__ Wl_rates, const float* __restrict__ bl_rates,
                            const float* __restrict__ Wr_rates,
                            const float* __restrict__ Wl_rev,  const float* __restrict__ bl_rev,
                            const float* __restrict__ Wr_rev,
                            const float* __restrict__ Wl_fol,  const float* __restrict__ bl_fol,
                            const float* __restrict__ Wr_fol) {
    int o = blockIdx.x;    // 0..127 (output dim)
    int k = threadIdx.x;   // 0..127 (input dim)
    g_WT[0 * D * D + k * D + o] = Wl_rates[o * D + k];
    g_WT[1 * D * D + k * D + o] = Wr_rates[o * D + k];
    g_WT[2 * D * D + k * D + o] = 0.5f * Wl_rev[o * D + k];
    g_WT[3 * D * D + k * D + o] = 0.5f * Wl_fol[o * D + k];
    g_WT[4 * D * D + k * D + o] = 0.5f * (Wr_rev[o * D + k] + Wr_fol[o * D + k]);
    if (k == 0) {
        g_bias[o]     = bl_rates[o];
        g_bias[D + o] = 0.5f * (bl_rev[o] + bl_fol[o]);
    }
}

// ---------------- warp-per-edge scatter-add (vector red.v4) ----------------
__global__ void scatter_kernel(const float* __restrict__ x_src,
                               const int* __restrict__ ei, int E, int rel) {
    int gw   = (int)((blockIdx.x * (size_t)blockDim.x + threadIdx.x) >> 5);
    int lane = threadIdx.x & 31;
    if (gw >= E) return;
    int src = ei[gw];       // ei[0][e]
    int dst = ei[E + gw];   // ei[1][e]
    float4 v = ((const float4*)(x_src + (size_t)src * D))[lane];
    float* a = &g_agg[rel][(size_t)dst * D] + lane * 4;
    // sm_90+: one vectorized reduction instead of 4 scalar RED.ADD.F32
    asm volatile("red.global.add.v4.f32 [%0], {%1, %2, %3, %4};"
                 :: "l"(a), "f"(v.x), "f"(v.y), "f"(v.z), "f"(v.w)
                 : "memory");
    if (lane == 0) atomicAdd(&g_cnt[rel][dst], 1);
}

// ---------------- fused multi-term GEMM epilogue ---------------------------
// out[n][o] = sum_t dot(in_t[n] * scale_t[n], WT_t[:][o]) + bias[o]
// All T weight matrices live in SMEM ([k][o]-transposed -> conflict-free LDS).
// 256 threads: ty=tid/32 -> node group (NPT nodes), tx=tid%32 -> 4 output dims.
template <int T, int NT>
__global__ void out_kernel(float* __restrict__ out, int nNodes,
                           const float* __restrict__ in0, const int* __restrict__ c0,
                           const float* __restrict__ in1, const int* __restrict__ c1,
                           const float* __restrict__ in2, const int* __restrict__ c2,
                           const float* __restrict__ WT, const float* __restrict__ bias) {
    extern __shared__ float smem[];
    float* sW  = smem;                 // T * D * D
    float* sIn = smem + T * D * D;     // T * NT * D
    const int tid = threadIdx.x;       // 256 threads
    const int tx  = tid & 31;
    const int ty  = tid >> 5;
    constexpr int NPT = NT / 8;

    // load all T weight matrices once per block
    {
        const float4* src  = (const float4*)WT;
        float4*       dstp = (float4*)sW;
        for (int i = tid; i < T * D * D / 4; i += 256) dstp[i] = src[i];
    }

    float4 b4 = ((const float4*)bias)[tx];

    int nTiles = (nNodes + NT - 1) / NT;
    for (int tile = blockIdx.x; tile < nTiles; tile += gridDim.x) {
        __syncthreads();   // previous iter finished reading sIn (1st iter: after W load)
        int base = tile * NT;
        // stage inputs (mean-scale folded in here)
        for (int j = tid; j < T * NT * 32; j += 256) {
            int t  = j / (NT * 32);
            int r  = j - t * NT * 32;
            int i  = r >> 5;
            int kk = r & 31;
            int node = base + i;
            float4 v = make_float4(0.f, 0.f, 0.f, 0.f);
            const float* inp = (t == 0) ? in0 : ((t == 1) ? in1 : in2);
            const int*   cp  = (t == 0) ? c0  : ((t == 1) ? c1  : c2);
            if (node < nNodes) {
                v = ((const float4*)inp)[node * 32 + kk];
                if (cp) {
                    float s = 1.0f / fmaxf((float)cp[node], 1.0f);
                    v.x *= s; v.y *= s; v.z *= s; v.w *= s;
                }
            }
            ((float4*)sIn)[j] = v;
        }
        __syncthreads();

        float4 acc[NPT];
        #pragma unroll
        for (int i = 0; i < NPT; i++) acc[i] = make_float4(0.f, 0.f, 0.f, 0.f);

        #pragma unroll 1
        for (int t = 0; t < T; t++) {
            const float* w  = sW + t * D * D;
            const float* sx = sIn + (t * NT + ty * NPT) * D;
            #pragma unroll 8
            for (int k4 = 0; k4 < 32; k4++) {
                float4 w0 = ((const float4*)(w + (k4 * 4 + 0) * D))[tx];
                float4 w1 = ((const float4*)(w + (k4 * 4 + 1) * D))[tx];
                float4 w2 = ((const float4*)(w + (k4 * 4 + 2) * D))[tx];
                float4 w3 = ((const float4*)(w + (k4 * 4 + 3) * D))[tx];
                #pragma unroll
                for (int i = 0; i < NPT; i++) {
                    float4 xv = ((const float4*)(sx + i * D))[k4];  // broadcast within warp
                    acc[i].x += xv.x * w0.x + xv.y * w1.x + xv.z * w2.x + xv.w * w3.x;
                    acc[i].y += xv.x * w0.y + xv.y * w1.y + xv.z * w2.y + xv.w * w3.y;
                    acc[i].z += xv.x * w0.z + xv.y * w1.z + xv.z * w2.z + xv.w * w3.z;
                    acc[i].w += xv.x * w0.w + xv.y * w1.w + xv.z * w2.w + xv.w * w3.w;
                }
            }
        }

        #pragma unroll
        for (int i = 0; i < NPT; i++) {
            int node = base + ty * NPT + i;
            if (node < nNodes) {
                float4 o4 = make_float4(acc[i].x + b4.x, acc[i].y + b4.y,
                                        acc[i].z + b4.z, acc[i].w + b4.w);
                ((float4*)(out + (size_t)node * D))[tx] = o4;
            }
        }
    }
}

// ---------------------------------------------------------------------------
extern "C" void kernel_launch(void* const* d_in, const int* in_sizes, int n_in,
                              void* d_out, int out_size) {
    const float* x_user   = (const float*)d_in[0];
    const float* x_item   = (const float*)d_in[1];
    const int*   ei_rates = (const int*)d_in[2];
    const int*   ei_rev   = (const int*)d_in[3];
    const int*   ei_fol   = (const int*)d_in[4];
    const float* Wl_rates = (const float*)d_in[5];
    const float* bl_rates = (const float*)d_in[6];
    const float* Wr_rates = (const float*)d_in[7];
    const float* Wl_rev   = (const float*)d_in[8];
    const float* bl_rev   = (const float*)d_in[9];
    const float* Wr_rev   = (const float*)d_in[10];
    const float* Wl_fol   = (const float*)d_in[11];
    const float* bl_fol   = (const float*)d_in[12];
    const float* Wr_fol   = (const float*)d_in[13];

    int E0 = in_sizes[2] / 2;
    int E1 = in_sizes[3] / 2;
    int E2 = in_sizes[4] / 2;

    float* out_user = (float*)d_out;                          // reference returns (out_user, out_item)
    float* out_item = (float*)d_out + (size_t)NN * D;

    float* agg; int* cnt; float* WT; float* bias;
    cudaGetSymbolAddress((void**)&agg,  g_agg);
    cudaGetSymbolAddress((void**)&cnt,  g_cnt);
    cudaGetSymbolAddress((void**)&WT,   g_WT);
    cudaGetSymbolAddress((void**)&bias, g_bias);

    // smem sizes for the two out_kernel instantiations
    const int SMEM2 = (2 * D * D + 2 * 32 * D) * 4;   // 163840 B
    const int SMEM3 = (3 * D * D + 3 * 16 * D) * 4;   // 221184 B
    cudaFuncSetAttribute((const void*)out_kernel<2, 32>,
                         cudaFuncAttributeMaxDynamicSharedMemorySize, SMEM2);
    cudaFuncSetAttribute((const void*)out_kernel<3, 16>,
                         cudaFuncAttributeMaxDynamicSharedMemorySize, SMEM3);

    zero_kernel<<<512, 256>>>();
    prep_kernel<<<128, 128>>>(Wl_rates, bl_rates, Wr_rates,
                              Wl_rev, bl_rev, Wr_rev,
                              Wl_fol, bl_fol, Wr_fol);

    // rates: user -> item ; rev: item -> user ; follows: user -> user
    scatter_kernel<<<(E0 * 32 + 255) / 256, 256>>>(x_user, ei_rates, E0, 0);
    scatter_kernel<<<(E1 * 32 + 255) / 256, 256>>>(x_item, ei_rev,   E1, 1);
    scatter_kernel<<<(E2 * 32 + 255) / 256, 256>>>(x_user, ei_fol,   E2, 2);

    // out_item = mean_rates @ Wl_rates^T + bl_rates + x_item @ Wr_rates^T
    out_kernel<2, 32><<<148, 256, SMEM2>>>(out_item, NN,
                                           agg + 0 * (size_t)NN * D, cnt + 0 * NN,
                                           x_item, nullptr,
                                           nullptr, nullptr,
                                           WT + 0 * D * D, bias);
    // out_user = .5*(mean_rev@Wl_rev^T + bl_rev + x_user@Wr_rev^T
    //              + mean_fol@Wl_fol^T + bl_fol + x_user@Wr_fol^T)
    //          (0.5 and Wr_rev+Wr_fol pre-folded into WT[2..4] / bias[D..2D))
    out_kernel<3, 16><<<148, 256, SMEM3>>>(out_user, NN,
                                           agg + 1 * (size_t)NN * D, cnt + 1 * NN,
                                           agg + 2 * (size_t)NN * D, cnt + 2 * NN,
                                           x_user, nullptr,
                                           WT + 2 * D * D, bias + D);
}

// round 7
// speedup vs baseline: 1.0896x; 1.0896x over previous
#include <cuda_runtime.h>

#define D 128
#define NN 50000

// ---------------- device scratch (no runtime allocation allowed) -------------
__device__ float g_agg[3][(size_t)NN * D];   // per-relation scatter accumulators
__device__ int   g_cnt[3][NN];               // per-relation in-degree counts
__device__ float g_WT[5 * D * D];            // transposed / pre-scaled weights
                                             // [0]=Wl_rates^T [1]=Wr_rates^T
                                             // [2]=.5*Wl_rev^T [3]=.5*Wl_fol^T [4]=.5*(Wr_rev+Wr_fol)^T
__device__ float g_bias[2 * D];              // [0:D)=bl_rates(item), [D:2D)=.5*(bl_rev+bl_fol)(user)

// ---------------- packed-fp32 FMA (SASS FFMA2; 2x fp32 throughput) ----------
__device__ __forceinline__ void fma2(unsigned long long& d,
                                     unsigned long long a, unsigned long long b) {
    asm("fma.rn.f32x2 %0, %1, %2, %0;" : "+l"(d) : "l"(a), "l"(b));
}

// ---------------- combined init: zero accumulators + bias-init output -------
// (must run every launch: graph replays accumulate via red.global)
__global__ void init_kernel(float* __restrict__ out) {
    size_t stride = (size_t)gridDim.x * blockDim.x;
    size_t i = (size_t)blockIdx.x * blockDim.x + threadIdx.x;
    // zero agg
    float4* p = (float4*)g_agg;
    const size_t n4 = (size_t)3 * NN * D / 4;
    for (size_t j = i; j < n4; j += stride) p[j] = make_float4(0.f, 0.f, 0.f, 0.f);
    // zero cnt
    int4* q = (int4*)g_cnt;
    const size_t c4 = (size_t)3 * NN / 4;
    for (size_t j = i; j < c4; j += stride) q[j] = make_int4(0, 0, 0, 0);
    // bias-init out: rows [0,NN) = user (g_bias+D), rows [NN,2NN) = item (g_bias)
    const size_t o4 = (size_t)2 * NN * 32;   // float4 count
    for (size_t j = i; j < o4; j += stride) {
        size_t row = j >> 5;
        int    kk  = (int)(j & 31);
        const float4* b = (const float4*)((row < NN) ? (g_bias + D) : g_bias);
        ((float4*)out)[j] = b[kk];
    }
}

// ---------------- build transposed & pre-scaled weights + fused biases -------
__global__ void prep_kernel(const float* __restrict__ Wl_rates, const float* __restrict__ bl_rates,
                            const float* __restrict__ Wr_rates,
                            const float* __restrict__ Wl_rev,  const float* __restrict__ bl_rev,
                            const float* __restrict__ Wr_rev,
                            const float* __restrict__ Wl_fol,  const float* __restrict__ bl_fol,
                            const float* __restrict__ Wr_fol) {
    int o = blockIdx.x;    // 0..127 (output dim)
    int k = threadIdx.x;   // 0..127 (input dim)
    g_WT[0 * D * D + k * D + o] = Wl_rates[o * D + k];
    g_WT[1 * D * D + k * D + o] = Wr_rates[o * D + k];
    g_WT[2 * D * D + k * D + o] = 0.5f * Wl_rev[o * D + k];
    g_WT[3 * D * D + k * D + o] = 0.5f * Wl_fol[o * D + k];
    g_WT[4 * D * D + k * D + o] = 0.5f * (Wr_rev[o * D + k] + Wr_fol[o * D + k]);
    if (k == 0) {
        g_bias[o]     = bl_rates[o];
        g_bias[D + o] = 0.5f * (bl_rev[o] + bl_fol[o]);
    }
}

// ---------------- warp-per-edge scatter-add (vector red.v4) ----------------
__global__ void scatter_kernel(const float* __restrict__ x_src,
                               const int* __restrict__ ei, int E, int rel) {
    int gw   = (int)((blockIdx.x * (size_t)blockDim.x + threadIdx.x) >> 5);
    int lane = threadIdx.x & 31;
    if (gw >= E) return;
    int src = ei[gw];       // ei[0][e]
    int dst = ei[E + gw];   // ei[1][e]
    float4 v = ((const float4*)(x_src + (size_t)src * D))[lane];
    float* a = &g_agg[rel][(size_t)dst * D] + lane * 4;
    asm volatile("red.global.add.v4.f32 [%0], {%1, %2, %3, %4};"
                 :: "l"(a), "f"(v.x), "f"(v.y), "f"(v.z), "f"(v.w)
                 : "memory");
    if (lane == 0) atomicAdd(&g_cnt[rel][dst], 1);
}

// ---------------- single-matrix GEMM pass: out += (in * scale?) @ WT -------
// W [k][o] resident in SMEM (read as packed (o,o+1) pairs -> no pack insts).
// x staged in SMEM pre-duplicated (x,x) pairs, mean-scale folded in.
// Inner loop is pure fma.rn.f32x2 (FFMA2). Accumulate to out via red.v4.
template <bool HAS_CNT>
__global__ void pass_kernel(float* __restrict__ out, const float* __restrict__ in,
                            const int* __restrict__ cnt, const float* __restrict__ WT,
                            int nNodes) {
    constexpr int NT = 32;   // nodes per tile
    extern __shared__ float smem[];
    float*  sW = smem;                         // D*D floats (64 KB)
    float2* sX = (float2*)(smem + D * D);      // NT*D dup pairs (32 KB)
    const int tid = threadIdx.x;               // 256 threads = 8 warps
    const int tx  = tid & 31;
    const int ty  = tid >> 5;

    // stage W once per block
    for (int i = tid; i < D * D / 4; i += 256)
        ((float4*)sW)[i] = ((const float4*)WT)[i];

    int nTiles = (nNodes + NT - 1) / NT;
    for (int tile = blockIdx.x; tile < nTiles; tile += gridDim.x) {
        __syncthreads();   // prev iter done reading sX (1st iter: orders sW writes)
        int base = tile * NT;
        // stage duplicated inputs
        for (int j = tid; j < NT * 32; j += 256) {
            int i  = j >> 5;
            int kk = j & 31;
            int node = base + i;
            float4 v = make_float4(0.f, 0.f, 0.f, 0.f);
            if (node < nNodes) {
                v = ((const float4*)in)[node * 32 + kk];
                if (HAS_CNT) {
                    float s = 1.0f / fmaxf((float)cnt[node], 1.0f);
                    v.x *= s; v.y *= s; v.z *= s; v.w *= s;
                }
            }
            float4* dstp = (float4*)&sX[i * D + kk * 4];
            dstp[0] = make_float4(v.x, v.x, v.y, v.y);
            dstp[1] = make_float4(v.z, v.z, v.w, v.w);
        }
        __syncthreads();

        // 4 nodes per warp; acc pairs = (o,o+1),(o+2,o+3) with o = tx*4
        unsigned long long acc[4][2];
        #pragma unroll
        for (int i = 0; i < 4; i++) { acc[i][0] = 0ull; acc[i][1] = 0ull; }

        #pragma unroll 4
        for (int k4 = 0; k4 < 32; k4++) {
            // weight pairs for 4 consecutive k rows; [tx] -> floats tx*4..tx*4+3
            ulonglong2 w0 = ((const ulonglong2*)(sW + (k4 * 4 + 0) * D))[tx];
            ulonglong2 w1 = ((const ulonglong2*)(sW + (k4 * 4 + 1) * D))[tx];
            ulonglong2 w2 = ((const ulonglong2*)(sW + (k4 * 4 + 2) * D))[tx];
            ulonglong2 w3 = ((const ulonglong2*)(sW + (k4 * 4 + 3) * D))[tx];
            #pragma unroll
            for (int i = 0; i < 4; i++) {
                const ulonglong2* xr =
                    (const ulonglong2*)&sX[(ty * 4 + i) * D + k4 * 4];
                ulonglong2 xa = xr[0];   // dup(x[4k4+0]), dup(x[4k4+1])
                ulonglong2 xb = xr[1];   // dup(x[4k4+2]), dup(x[4k4+3])
                fma2(acc[i][0], xa.x, w0.x); fma2(acc[i][1], xa.x, w0.y);
                fma2(acc[i][0], xa.y, w1.x); fma2(acc[i][1], xa.y, w1.y);
                fma2(acc[i][0], xb.x, w2.x); fma2(acc[i][1], xb.x, w2.y);
                fma2(acc[i][0], xb.y, w3.x); fma2(acc[i][1], xb.y, w3.y);
            }
        }

        #pragma unroll
        for (int i = 0; i < 4; i++) {
            int node = base + ty * 4 + i;
            if (node < nNodes) {
                float* o = out + (size_t)node * D + tx * 4;
                float v0 = __uint_as_float((unsigned)(acc[i][0] & 0xffffffffull));
                float v1 = __uint_as_float((unsigned)(acc[i][0] >> 32));
                float v2 = __uint_as_float((unsigned)(acc[i][1] & 0xffffffffull));
                float v3 = __uint_as_float((unsigned)(acc[i][1] >> 32));
                asm volatile("red.global.add.v4.f32 [%0], {%1, %2, %3, %4};"
                             :: "l"(o), "f"(v0), "f"(v1), "f"(v2), "f"(v3)
                             : "memory");
            }
        }
    }
}

// ---------------------------------------------------------------------------
extern "C" void kernel_launch(void* const* d_in, const int* in_sizes, int n_in,
                              void* d_out, int out_size) {
    const float* x_user   = (const float*)d_in[0];
    const float* x_item   = (const float*)d_in[1];
    const int*   ei_rates = (const int*)d_in[2];
    const int*   ei_rev   = (const int*)d_in[3];
    const int*   ei_fol   = (const int*)d_in[4];
    const float* Wl_rates = (const float*)d_in[5];
    const float* bl_rates = (const float*)d_in[6];
    const float* Wr_rates = (const float*)d_in[7];
    const float* Wl_rev   = (const float*)d_in[8];
    const float* bl_rev   = (const float*)d_in[9];
    const float* Wr_rev   = (const float*)d_in[10];
    const float* Wl_fol   = (const float*)d_in[11];
    const float* bl_fol   = (const float*)d_in[12];
    const float* Wr_fol   = (const float*)d_in[13];

    int E0 = in_sizes[2] / 2;
    int E1 = in_sizes[3] / 2;
    int E2 = in_sizes[4] / 2;

    float* out_user = (float*)d_out;
    float* out_item = (float*)d_out + (size_t)NN * D;

    float* agg; int* cnt; float* WT;
    cudaGetSymbolAddress((void**)&agg, g_agg);
    cudaGetSymbolAddress((void**)&cnt, g_cnt);
    cudaGetSymbolAddress((void**)&WT,  g_WT);

    const int PASS_SMEM = (D * D) * 4 + 32 * D * 8;   // 65536 + 32768 = 98304
    cudaFuncSetAttribute((const void*)pass_kernel<true>,
                         cudaFuncAttributeMaxDynamicSharedMemorySize, PASS_SMEM);
    cudaFuncSetAttribute((const void*)pass_kernel<false>,
                         cudaFuncAttributeMaxDynamicSharedMemorySize, PASS_SMEM);

    prep_kernel<<<128, 128>>>(Wl_rates, bl_rates, Wr_rates,
                              Wl_rev, bl_rev, Wr_rev,
                              Wl_fol, bl_fol, Wr_fol);
    init_kernel<<<1024, 256>>>((float*)d_out);

    // rates: user -> item ; rev: item -> user ; follows: user -> user
    scatter_kernel<<<(E0 * 32 + 255) / 256, 256>>>(x_user, ei_rates, E0, 0);
    scatter_kernel<<<(E1 * 32 + 255) / 256, 256>>>(x_item, ei_rev,   E1, 1);
    scatter_kernel<<<(E2 * 32 + 255) / 256, 256>>>(x_user, ei_fol,   E2, 2);

    const int PG = 296;   // 2 blocks/SM
    // out_item += mean_rates @ Wl_rates^T  and  x_item @ Wr_rates^T
    pass_kernel<true><<<PG, 256, PASS_SMEM>>>(out_item, agg + 0 * (size_t)NN * D,
                                              cnt + 0 * NN, WT + 0 * D * D, NN);
    pass_kernel<false><<<PG, 256, PASS_SMEM>>>(out_item, x_item,
                                               nullptr, WT + 1 * D * D, NN);
    // out_user += .5*mean_rev@Wl_rev^T + .5*mean_fol@Wl_fol^T + x_user@(.5*(Wr_rev+Wr_fol))^T
    pass_kernel<true><<<PG, 256, PASS_SMEM>>>(out_user, agg + 1 * (size_t)NN * D,
                                              cnt + 1 * NN, WT + 2 * D * D, NN);
    pass_kernel<true><<<PG, 256, PASS_SMEM>>>(out_user, agg + 2 * (size_t)NN * D,
                                              cnt + 2 * NN, WT + 3 * D * D, NN);
    pass_kernel<false><<<PG, 256, PASS_SMEM>>>(out_user, x_user,
                                               nullptr, WT + 4 * D * D, NN);
}

// round 8
// speedup vs baseline: 1.4160x; 1.2995x over previous
#include <cuda_runtime.h>

#define D 128
#define NN 50000
typedef unsigned long long ULL;

// ---------------- device scratch (no runtime allocation allowed) -------------
__device__ float g_agg[3][(size_t)NN * D];   // per-relation scatter accumulators
__device__ int   g_cnt[3][NN];               // per-relation in-degree counts
__device__ float g_WT[5 * D * D];            // transposed / pre-scaled weights [k][o]
                                             // [0]=Wl_rates^T [1]=Wr_rates^T   (item: K=256)
                                             // [2]=.5*Wl_rev^T [3]=.5*Wl_fol^T [4]=.5*(Wr_rev+Wr_fol)^T (user: K=384)
__device__ float g_bias[2 * D];              // [0:D)=bl_rates(item), [D:2D)=.5*(bl_rev+bl_fol)(user)

// ---------------- packed-fp32 helpers (SASS FFMA2 path) ---------------------
__device__ __forceinline__ void fma2(ULL& d, ULL a, ULL b) {
    asm("fma.rn.f32x2 %0, %1, %2, %0;" : "+l"(d) : "l"(a), "l"(b));
}
__device__ __forceinline__ ULL pack2(float lo, float hi) {
    ULL r; asm("mov.b64 %0, {%1, %2};" : "=l"(r) : "f"(lo), "f"(hi)); return r;
}
__device__ __forceinline__ void unpack2(ULL v, float& lo, float& hi) {
    asm("mov.b64 {%0, %1}, %2;" : "=f"(lo), "=f"(hi) : "l"(v));
}

// ---------------- init: zero accumulators + counts (every replay) -----------
__global__ void init_kernel() {
    size_t stride = (size_t)gridDim.x * blockDim.x;
    size_t i = (size_t)blockIdx.x * blockDim.x + threadIdx.x;
    float4* p = (float4*)g_agg;
    const size_t n4 = (size_t)3 * NN * D / 4;
    for (size_t j = i; j < n4; j += stride) p[j] = make_float4(0.f, 0.f, 0.f, 0.f);
    int4* q = (int4*)g_cnt;
    const size_t c4 = (size_t)3 * NN / 4;
    for (size_t j = i; j < c4; j += stride) q[j] = make_int4(0, 0, 0, 0);
}

// ---------------- build transposed & pre-scaled weights + fused biases ------
__global__ void prep_kernel(const float* __restrict__ Wl_rates, const float* __restrict__ bl_rates,
                            const float* __restrict__ Wr_rates,
                            const float* __restrict__ Wl_rev,  const float* __restrict__ bl_rev,
                            const float* __restrict__ Wr_rev,
                            const float* __restrict__ Wl_fol,  const float* __restrict__ bl_fol,
                            const float* __restrict__ Wr_fol) {
    int o = blockIdx.x;    // 0..127 output dim
    int k = threadIdx.x;   // 0..127 input dim
    g_WT[0 * D * D + k * D + o] = Wl_rates[o * D + k];
    g_WT[1 * D * D + k * D + o] = Wr_rates[o * D + k];
    g_WT[2 * D * D + k * D + o] = 0.5f * Wl_rev[o * D + k];
    g_WT[3 * D * D + k * D + o] = 0.5f * Wl_fol[o * D + k];
    g_WT[4 * D * D + k * D + o] = 0.5f * (Wr_rev[o * D + k] + Wr_fol[o * D + k]);
    if (k == 0) {
        g_bias[o]     = bl_rates[o];
        g_bias[D + o] = 0.5f * (bl_rev[o] + bl_fol[o]);
    }
}

// ---------------- warp-per-edge scatter-add (vector red.v4) ----------------
__global__ void scatter_kernel(const float* __restrict__ x_src,
                               const int* __restrict__ ei, int E, int rel) {
    int gw   = (int)((blockIdx.x * (size_t)blockDim.x + threadIdx.x) >> 5);
    int lane = threadIdx.x & 31;
    if (gw >= E) return;
    int src = ei[gw];       // ei[0][e]
    int dst = ei[E + gw];   // ei[1][e]
    float4 v = ((const float4*)(x_src + (size_t)src * D))[lane];
    float* a = &g_agg[rel][(size_t)dst * D] + lane * 4;
    asm volatile("red.global.add.v4.f32 [%0], {%1, %2, %3, %4};"
                 :: "l"(a), "f"(v.x), "f"(v.y), "f"(v.z), "f"(v.w)
                 : "memory");
    if (lane == 0) atomicAdd(&g_cnt[rel][dst], 1);
}

// ---------------- combined concatenated-K GEMM --------------------------
// Tiles [0,782): out_user = [mean_rev|mean_fol|x_user](Nx384) @ WT_user + b_user
// Tiles [782,1564): out_item = [mean_rates|x_item](Nx256) @ WT_item + b_item
// Per tile: 64 nodes = 32 node-pairs. Per chunk (K=128): W chunk (64KB) staged
// to SMEM, x staged pair-interleaved (xi[k],xj[k]) as ULL.
// Warp = 4 pairs (8 nodes); lane = 4 outputs (o=tx*4). acc = f32x2(node_i,node_j).
// Inner 2k step: 2 W LDS.128 + 8 dup-movs + 4 pair LDS.128(broadcast) + 32 FFMA2
// -> FMA-pipe-bound (crossbar ~9 cyc < 16 FMA-pipe cyc per warp-2k).
__global__ void __launch_bounds__(256, 2)
gemm_kernel(float* __restrict__ outU, float* __restrict__ outI,
            const float* __restrict__ aggRev,   const int* __restrict__ cntRev,
            const float* __restrict__ aggFol,   const int* __restrict__ cntFol,
            const float* __restrict__ xU,
            const float* __restrict__ aggRates, const int* __restrict__ cntRates,
            const float* __restrict__ xI,
            const float* __restrict__ WT, const float* __restrict__ biasAll) {
    extern __shared__ float smem[];
    float* sW  = smem;                    // 128*128 floats (64 KB), one K-chunk
    ULL*   sXp = (ULL*)(smem + D * D);    // 32 pairs * 128 k (32 KB)
    const int tid = threadIdx.x;          // 256 threads = 8 warps
    const int tx  = tid & 31;
    const int wy  = tid >> 5;

    const int nTilesU = (NN + 63) / 64;       // 782
    const int nTilesT = 2 * nTilesU;

    for (int t = blockIdx.x; t < nTilesT; t += gridDim.x) {
        bool isU  = (t < nTilesU);
        int tile  = isU ? t : t - nTilesU;
        int nCh   = isU ? 3 : 2;
        const float* WTj  = WT + (isU ? 2 * D * D : 0);
        const float* bias = biasAll + (isU ? D : 0);
        float* out = isU ? outU : outI;
        int base = tile * 64;

        float4 b4 = ((const float4*)bias)[tx];

        ULL acc[4][4];
        #pragma unroll
        for (int p = 0; p < 4; p++)
            #pragma unroll
            for (int o = 0; o < 4; o++) acc[p][o] = 0ull;

        for (int ch = 0; ch < nCh; ch++) {
            const float* inp;
            const int*   cp;
            if (isU) {
                inp = (ch == 0) ? aggRev : (ch == 1) ? aggFol : xU;
                cp  = (ch == 0) ? cntRev : (ch == 1) ? cntFol : (const int*)0;
            } else {
                inp = (ch == 0) ? aggRates : xI;
                cp  = (ch == 0) ? cntRates : (const int*)0;
            }
            const float4* wsrc = (const float4*)(WTj + ch * D * D);

            __syncthreads();   // prev chunk's sW/sXp fully consumed
            // stage W chunk (64 KB)
            for (int i = tid; i < D * D / 4; i += 256)
                ((float4*)sW)[i] = wsrc[i];
            // stage x, pair-interleaved: unit = (pair, k4)
            for (int u = tid; u < 32 * 32; u += 256) {
                int pair = u >> 5;
                int k4   = u & 31;
                int na = base + pair * 2, nb = na + 1;
                float4 a = make_float4(0.f, 0.f, 0.f, 0.f);
                float4 b = make_float4(0.f, 0.f, 0.f, 0.f);
                if (na < NN) {
                    a = ((const float4*)inp)[na * 32 + k4];
                    if (cp) { float s = 1.f / fmaxf((float)cp[na], 1.f);
                              a.x *= s; a.y *= s; a.z *= s; a.w *= s; }
                }
                if (nb < NN) {
                    b = ((const float4*)inp)[nb * 32 + k4];
                    if (cp) { float s = 1.f / fmaxf((float)cp[nb], 1.f);
                              b.x *= s; b.y *= s; b.z *= s; b.w *= s; }
                }
                ulonglong2* dst = (ulonglong2*)&sXp[pair * D + k4 * 4];
                ulonglong2 d0, d1;
                d0.x = pack2(a.x, b.x); d0.y = pack2(a.y, b.y);
                d1.x = pack2(a.z, b.z); d1.y = pack2(a.w, b.w);
                dst[0] = d0; dst[1] = d1;
            }
            __syncthreads();

            // compute this K-chunk: warp wy owns pairs wy*4 .. wy*4+3
            #pragma unroll 2
            for (int k2 = 0; k2 < 64; k2++) {
                float4 wA = ((const float4*)(sW + (2 * k2 + 0) * D))[tx];
                float4 wB = ((const float4*)(sW + (2 * k2 + 1) * D))[tx];
                ULL wa0 = pack2(wA.x, wA.x), wa1 = pack2(wA.y, wA.y);
                ULL wa2 = pack2(wA.z, wA.z), wa3 = pack2(wA.w, wA.w);
                ULL wb0 = pack2(wB.x, wB.x), wb1 = pack2(wB.y, wB.y);
                ULL wb2 = pack2(wB.z, wB.z), wb3 = pack2(wB.w, wB.w);
                #pragma unroll
                for (int p = 0; p < 4; p++) {
                    ulonglong2 px = *(const ulonglong2*)&sXp[(wy * 4 + p) * D + k2 * 2];
                    fma2(acc[p][0], px.x, wa0); fma2(acc[p][1], px.x, wa1);
                    fma2(acc[p][2], px.x, wa2); fma2(acc[p][3], px.x, wa3);
                    fma2(acc[p][0], px.y, wb0); fma2(acc[p][1], px.y, wb1);
                    fma2(acc[p][2], px.y, wb2); fma2(acc[p][3], px.y, wb3);
                }
            }
        }

        // store: unpack (node_i, node_j) halves, add bias
        #pragma unroll
        for (int p = 0; p < 4; p++) {
            int na = base + (wy * 4 + p) * 2, nb = na + 1;
            float l0, h0, l1, h1, l2, h2, l3, h3;
            unpack2(acc[p][0], l0, h0); unpack2(acc[p][1], l1, h1);
            unpack2(acc[p][2], l2, h2); unpack2(acc[p][3], l3, h3);
            if (na < NN)
                ((float4*)(out + (size_t)na * D))[tx] =
                    make_float4(l0 + b4.x, l1 + b4.y, l2 + b4.z, l3 + b4.w);
            if (nb < NN)
                ((float4*)(out + (size_t)nb * D))[tx] =
                    make_float4(h0 + b4.x, h1 + b4.y, h2 + b4.z, h3 + b4.w);
        }
    }
}

// ---------------------------------------------------------------------------
extern "C" void kernel_launch(void* const* d_in, const int* in_sizes, int n_in,
                              void* d_out, int out_size) {
    const float* x_user   = (const float*)d_in[0];
    const float* x_item   = (const float*)d_in[1];
    const int*   ei_rates = (const int*)d_in[2];
    const int*   ei_rev   = (const int*)d_in[3];
    const int*   ei_fol   = (const int*)d_in[4];
    const float* Wl_rates = (const float*)d_in[5];
    const float* bl_rates = (const float*)d_in[6];
    const float* Wr_rates = (const float*)d_in[7];
    const float* Wl_rev   = (const float*)d_in[8];
    const float* bl_rev   = (const float*)d_in[9];
    const float* Wr_rev   = (const float*)d_in[10];
    const float* Wl_fol   = (const float*)d_in[11];
    const float* bl_fol   = (const float*)d_in[12];
    const float* Wr_fol   = (const float*)d_in[13];

    int E0 = in_sizes[2] / 2;
    int E1 = in_sizes[3] / 2;
    int E2 = in_sizes[4] / 2;

    float* out_user = (float*)d_out;
    float* out_item = (float*)d_out + (size_t)NN * D;

    float* agg; int* cnt; float* WT; float* bias;
    cudaGetSymbolAddress((void**)&agg,  g_agg);
    cudaGetSymbolAddress((void**)&cnt,  g_cnt);
    cudaGetSymbolAddress((void**)&WT,   g_WT);
    cudaGetSymbolAddress((void**)&bias, g_bias);

    const int GEMM_SMEM = D * D * 4 + 32 * D * 8;   // 65536 + 32768 = 98304
    cudaFuncSetAttribute((const void*)gemm_kernel,
                         cudaFuncAttributeMaxDynamicSharedMemorySize, GEMM_SMEM);

    prep_kernel<<<128, 128>>>(Wl_rates, bl_rates, Wr_rates,
                              Wl_rev, bl_rev, Wr_rev,
                              Wl_fol, bl_fol, Wr_fol);
    init_kernel<<<1024, 256>>>();

    // rates: user -> item ; rev: item -> user ; follows: user -> user
    scatter_kernel<<<(E0 * 32 + 255) / 256, 256>>>(x_user, ei_rates, E0, 0);
    scatter_kernel<<<(E1 * 32 + 255) / 256, 256>>>(x_item, ei_rev,   E1, 1);
    scatter_kernel<<<(E2 * 32 + 255) / 256, 256>>>(x_user, ei_fol,   E2, 2);

    gemm_kernel<<<296, 256, GEMM_SMEM>>>(out_user, out_item,
                                         agg + 1 * (size_t)NN * D, cnt + 1 * NN,   // rev
                                         agg + 2 * (size_t)NN * D, cnt + 2 * NN,   // fol
                                         x_user,
                                         agg + 0 * (size_t)NN * D, cnt + 0 * NN,   // rates
                                         x_item,
                                         WT, bias);
}